// round 11
// baseline (speedup 1.0000x reference)
#include <cuda_runtime.h>
#include <math.h>
#include <stdint.h>

// Problem constants
#define BB  4
#define TT  2048
#define DDM 512
#define HH  8
#define HDM 64
#define MM  (BB*TT)

// ---------------------------------------------------------------------------
// Scratch
// ---------------------------------------------------------------------------
static __device__ float g_qp [MM * DDM];
static __device__ float g_kp [MM * DDM];   // stored with d-pair interleave!
static __device__ float g_vp [MM * DDM];
static __device__ float g_ctx[MM * DDM];

// ---------------------------------------------------------------------------
// tf32 / async helpers (plain sm_80+ PTX — valid at compute_100)
// ---------------------------------------------------------------------------
__device__ __forceinline__ uint32_t tf32u(float x) {
    uint32_t r;
    asm("cvt.rna.tf32.f32 %0, %1;" : "=r"(r) : "f"(x));
    return r;
}
__device__ __forceinline__ float tf32f(float x) {
    return __uint_as_float(tf32u(x));
}
__device__ __forceinline__ uint32_t su32(const void* p) {
    uint32_t a;
    asm("{ .reg .u64 t; cvta.to.shared.u64 t, %1; cvt.u32.u64 %0, t; }" : "=r"(a) : "l"(p));
    return a;
}
__device__ __forceinline__ void cp16(uint32_t s, const void* g) {
    asm volatile("cp.async.cg.shared.global [%0], [%1], 16;" :: "r"(s), "l"(g) : "memory");
}
#define CP_COMMIT() asm volatile("cp.async.commit_group;" ::: "memory")
#define CP_WAIT0()  asm volatile("cp.async.wait_group 0;" ::: "memory")
#define CP_WAIT1()  asm volatile("cp.async.wait_group 1;" ::: "memory")

// D(4xf32) += A(4xtf32) * B(2xtf32), m16n8k8
#define MMA8(d, a, b) \
    asm volatile("mma.sync.aligned.m16n8k8.row.col.f32.tf32.tf32.f32 " \
        "{%0,%1,%2,%3}, {%4,%5,%6,%7}, {%8,%9}, {%0,%1,%2,%3};" \
        : "+f"((d)[0]), "+f"((d)[1]), "+f"((d)[2]), "+f"((d)[3]) \
        : "r"((a)[0]), "r"((a)[1]), "r"((a)[2]), "r"((a)[3]), \
          "r"((b)[0]), "r"((b)[1]))

// ---------------------------------------------------------------------------
// Kernel 1: projection GEMM  C[8192,512] = A @ W + bias   (tf32 HMMA)
// mode 1: z-batched qkv (z=1 writes K with d-pair interleave via coalesced
// shuffle-pair stores). mode 0: single GEMM g_ctx @ Wc + bc -> Cext.
// ---------------------------------------------------------------------------
__global__ __launch_bounds__(256)
void proj_mma(const float* __restrict__ Aq, const float* __restrict__ Ak,
              const float* __restrict__ Av,
              const float* __restrict__ Wq_, const float* __restrict__ Wk_,
              const float* __restrict__ bq_, const float* __restrict__ bk_,
              float* __restrict__ Cext, int mode)
{
    const int z = (mode == 1) ? blockIdx.z : 3;
    const float* A;
    const float* W;
    const float* bias;
    float* C;
    int round_out, permute_out;
    if (mode == 1) {
        A = (z == 0) ? Aq : (z == 1) ? Ak : Av;
        W = (z == 0) ? Wq_ : Wk_;
        bias = (z == 0) ? bq_ : bk_;
        C = (z == 0) ? g_qp : (z == 1) ? g_kp : g_vp;
        round_out = 1;
        permute_out = (z == 1);
    } else {
        A = g_ctx; W = Wq_; bias = bq_; C = Cext;
        round_out = 0; permute_out = 0;
    }

    __shared__ float sA[4 * 128 * 12];   // 24 KB
    __shared__ float sB[4 * 8 * 136];    // 17.4 KB

    const int tid  = threadIdx.x;
    const int wid  = tid >> 5;
    const int lane = tid & 31;
    const int g    = lane >> 2;
    const int c    = lane & 3;
    const int wm   = wid >> 2;
    const int wn   = wid & 3;
    const int m0   = blockIdx.y * 128;
    const int n0   = blockIdx.x * 128;

    int ar[4], ac4[4], bk_i[4], bn4[4];
    #pragma unroll
    for (int i = 0; i < 4; i++) {
        int idx = tid + 256 * i;
        ar[i]   = idx >> 3;      ac4[i] = idx & 7;
        bk_i[i] = idx >> 5;      bn4[i] = idx & 31;
    }

    float df[4][4][4];
    #pragma unroll
    for (int mt = 0; mt < 4; mt++)
        #pragma unroll
        for (int nt = 0; nt < 4; nt++)
            #pragma unroll
            for (int j = 0; j < 4; j++) df[mt][nt][j] = 0.f;

    float4 pa[4], pb[4];
    #pragma unroll
    for (int i = 0; i < 4; i++) {
        pa[i] = *(const float4*)&A[(size_t)(m0 + ar[i]) * DDM + ac4[i] * 4];
        pb[i] = *(const float4*)&W[(size_t)bk_i[i] * DDM + n0 + bn4[i] * 4];
    }

    for (int it = 0; it < 16; it++) {
        #pragma unroll
        for (int i = 0; i < 4; i++) {
            float4 v = pa[i];
            v.x = tf32f(v.x); v.y = tf32f(v.y); v.z = tf32f(v.z); v.w = tf32f(v.w);
            *(float4*)&sA[((ac4[i] >> 1) * 128 + ar[i]) * 12 + (ac4[i] & 1) * 4] = v;
            float4 u = pb[i];
            u.x = tf32f(u.x); u.y = tf32f(u.y); u.z = tf32f(u.z); u.w = tf32f(u.w);
            *(float4*)&sB[((bk_i[i] >> 3) * 8 + (bk_i[i] & 7)) * 136 + bn4[i] * 4] = u;
        }
        __syncthreads();

        if (it < 15) {
            const int kc = (it + 1) * 32;
            #pragma unroll
            for (int i = 0; i < 4; i++) {
                pa[i] = *(const float4*)&A[(size_t)(m0 + ar[i]) * DDM + kc + ac4[i] * 4];
                pb[i] = *(const float4*)&W[(size_t)(kc + bk_i[i]) * DDM + n0 + bn4[i] * 4];
            }
        }

        #pragma unroll
        for (int s4 = 0; s4 < 4; s4++) {
            uint32_t bf[4][2];
            #pragma unroll
            for (int nt = 0; nt < 4; nt++) {
                int n = wn * 32 + nt * 8 + g;
                bf[nt][0] = __float_as_uint(sB[(s4 * 8 + c)     * 136 + n]);
                bf[nt][1] = __float_as_uint(sB[(s4 * 8 + c + 4) * 136 + n]);
            }
            #pragma unroll
            for (int mt = 0; mt < 4; mt++) {
                int m = wm * 64 + mt * 16 + g;
                uint32_t af[4];
                af[0] = __float_as_uint(sA[(s4 * 128 + m)     * 12 + c]);
                af[1] = __float_as_uint(sA[(s4 * 128 + m + 8) * 12 + c]);
                af[2] = __float_as_uint(sA[(s4 * 128 + m)     * 12 + c + 4]);
                af[3] = __float_as_uint(sA[(s4 * 128 + m + 8) * 12 + c + 4]);
                #pragma unroll
                for (int nt = 0; nt < 4; nt++)
                    MMA8(df[mt][nt], af, bf[nt]);
            }
        }
        __syncthreads();
    }

    // K-interleave store offset within 8-block: lane c -> pair slot
    // c=0 -> 0, c=1 -> 4, c=2 -> 2, c=3 -> 6
    const int poff = ((c & 1) << 2) | ((c >> 1) << 1);

    #pragma unroll
    for (int nt = 0; nt < 4; nt++) {
        const int col = n0 + wn * 32 + nt * 8 + 2 * c;
        const float b0 = bias[col], b1 = bias[col + 1];
        #pragma unroll
        for (int mt = 0; mt < 4; mt++) {
            const int row = m0 + wm * 64 + mt * 16 + g;
            float o00 = df[mt][nt][0] + b0, o01 = df[mt][nt][1] + b1;
            float o10 = df[mt][nt][2] + b0, o11 = df[mt][nt][3] + b1;
            if (round_out) {
                o00 = tf32f(o00); o01 = tf32f(o01);
                o10 = tf32f(o10); o11 = tf32f(o11);
            }
            if (permute_out) {
                // pair-interleave: slot 2r holds (col r, col r+4).
                // lanes c and c^2 exchange one value -> coalesced float2 stores.
                float s0 = (c < 2) ? o01 : o00;
                float r0 = __shfl_xor_sync(0xffffffffu, s0, 2);
                float s1 = (c < 2) ? o11 : o10;
                float r1 = __shfl_xor_sync(0xffffffffu, s1, 2);
                float2 p0 = (c < 2) ? make_float2(o00, r0) : make_float2(r0, o01);
                float2 p1 = (c < 2) ? make_float2(o10, r1) : make_float2(r1, o11);
                const int colp = n0 + wn * 32 + nt * 8 + poff;
                *(float2*)&C[(size_t)row * DDM + colp]       = p0;
                *(float2*)&C[(size_t)(row + 8) * DDM + colp] = p1;
            } else {
                *(float2*)&C[(size_t)row * DDM + col]       = make_float2(o00, o01);
                *(float2*)&C[(size_t)(row + 8) * DDM + col] = make_float2(o10, o11);
            }
        }
    }
}

// ---------------------------------------------------------------------------
// Kernel 2: fused attention, tf32 HMMA, 512 threads / 16 warps.
// S-phase: warp = (head, q-half), K interleaved -> LDS.64 B-frags.
// ctx-phase: warp = (head, d-half) — both warps cover all 32 q, 32 d each
// (halves V-frag crossbar traffic vs q-split).
// ---------------------------------------------------------------------------
#define SKS 516                    // sK row stride (floats)
#define SVS 520                    // sV row stride
#define SES 36                     // sE q-row stride (32 k + 4 pad)
#define SEH (32 * SES)             // sE head stride
#define FA_SMEM_BYTES ((32*SKS + 32*SVS + 8*SEH) * 4)
#define L2E8 0.18033688f           // log2(e)/8

__global__ __launch_bounds__(512, 1)
void fa_kernel(void)
{
    extern __shared__ float sm[];
    float* sK = sm;                        // [32][516]  (d-pair-interleaved cols)
    float* sV = sm + 32 * SKS;             // [32][520]
    float* sE = sm + 32 * SKS + 32 * SVS;  // [8][32][36]

    const int tid  = threadIdx.x;
    const int wid  = tid >> 5;
    const int w    = wid & 7;              // head
    const int half = wid >> 3;             // S: q-half; ctx: d-half
    const int lane = tid & 31;
    const int g    = lane >> 2;
    const int c    = lane & 3;
    const int q0   = blockIdx.x * 32;
    const size_t bT = (size_t)blockIdx.y * TT;

    float* sEw = sE + w * SEH;
    const int wh = w * HDM;

    // staging map
    const int str  = tid >> 7;
    const int sc4  = tid & 127;
    const uint32_t sKa = su32(sK) + (str * SKS + sc4 * 4) * 4;
    const uint32_t sVa = su32(sV) + (str * SVS + sc4 * 4) * 4;
    const float* gK = g_kp + (bT + str) * DDM + sc4 * 4;
    const float* gV = g_vp + (bT + str) * DDM + sc4 * 4;

    // ---- persistent Q fragments (natural layout in g_qp): 16q x 64d ----
    uint32_t qf[8][4];
    {
        const size_t r0 = bT + q0 + half * 16 + g;
        #pragma unroll
        for (int ds = 0; ds < 8; ds++) {
            const int col = wh + ds * 8 + c;
            qf[ds][0] = __float_as_uint(g_qp[r0 * DDM + col]);
            qf[ds][1] = __float_as_uint(g_qp[(r0 + 8) * DDM + col]);
            qf[ds][2] = __float_as_uint(g_qp[r0 * DDM + col + 4]);
            qf[ds][3] = __float_as_uint(g_qp[(r0 + 8) * DDM + col + 4]);
        }
    }

    // ctx accumulators: 32 q x 32 d (d-half) = [2 mt][4 nt][4]
    float ctxf[2][4][4];
    #pragma unroll
    for (int mt = 0; mt < 2; mt++)
        #pragma unroll
        for (int nt = 0; nt < 4; nt++)
            #pragma unroll
            for (int j = 0; j < 4; j++) ctxf[mt][nt][j] = 0.f;

    // ---- prologue: async-issue K(0) ----
    #pragma unroll
    for (int i = 0; i < 8; i++)
        cp16(sKa + i * (4 * SKS * 4), gK + (size_t)(4 * i) * DDM);
    CP_COMMIT();

    for (int kt = 0; kt < TT / 32; kt++) {
        const int k0 = kt * 32;

        CP_WAIT0();
        __syncthreads();     // B1: K visible; ctx(kt-1) done with sV/sE

        // ---- async-issue V(kt) ----
        #pragma unroll
        for (int i = 0; i < 8; i++)
            cp16(sVa + i * (4 * SVS * 4), gV + (size_t)(k0 + 4 * i) * DDM);
        CP_COMMIT();

        // ---- S = Q_w[16x64] @ K_w^T[64x32]; B-frags via LDS.64 ----
        float sf[4][4];
        #pragma unroll
        for (int nt = 0; nt < 4; nt++)
            #pragma unroll
            for (int j = 0; j < 4; j++) sf[nt][j] = 0.f;

        #pragma unroll
        for (int ds = 0; ds < 8; ds++) {
            const int dcol = wh + ds * 8 + 2 * c;   // interleaved: (c, c+4) adjacent
            #pragma unroll
            for (int nt = 0; nt < 4; nt++) {
                const int krow = nt * 8 + g;
                float2 bp = *(const float2*)&sK[krow * SKS + dcol];
                uint32_t bf[2];
                bf[0] = __float_as_uint(bp.x);
                bf[1] = __float_as_uint(bp.y);
                MMA8(sf[nt], qf[ds], bf);
            }
        }

        // ---- write S frags to exchange buffer ----
        #pragma unroll
        for (int nt = 0; nt < 4; nt++) {
            float* e = &sEw[(half * 16 + g) * SES + nt * 8 + 2 * c];
            *(float2*)e             = make_float2(sf[nt][0], sf[nt][1]);
            *(float2*)(e + 8 * SES) = make_float2(sf[nt][2], sf[nt][3]);
        }
        __syncthreads();     // B2

        // ---- async-issue K(kt+1) ----
        {
            const int kn = ((kt + 1) & 63) * 32;
            #pragma unroll
            for (int i = 0; i < 8; i++)
                cp16(sKa + i * (4 * SKS * 4), gK + (size_t)(kn + 4 * i) * DDM);
            CP_COMMIT();
        }

        // ---- softmax over heads ----
        {
            const int q  = tid >> 4;
            const int kb = (tid & 15) * 2;
            float2 v[8];
            #pragma unroll
            for (int h = 0; h < 8; h++)
                v[h] = *(const float2*)&sE[h * SEH + q * SES + kb];
            #pragma unroll
            for (int j = 0; j < 2; j++) {
                float m = ((float*)&v[0])[j];
                #pragma unroll
                for (int h = 1; h < 8; h++) m = fmaxf(m, ((float*)&v[h])[j]);
                const float ms = m * L2E8;
                float s = 0.f;
                #pragma unroll
                for (int h = 0; h < 8; h++) {
                    float e = exp2f(fmaf(((float*)&v[h])[j], L2E8, -ms));
                    ((float*)&v[h])[j] = e; s += e;
                }
                const float inv = 1.f / s;
                #pragma unroll
                for (int h = 0; h < 8; h++) ((float*)&v[h])[j] *= inv;
            }
            #pragma unroll
            for (int h = 0; h < 8; h++) {
                float2 o = v[h];
                o.x = tf32f(o.x); o.y = tf32f(o.y);
                *(float2*)&sE[h * SEH + q * SES + kb] = o;
            }
        }

        CP_WAIT1();
        __syncthreads();     // B3: attn + V visible

        // ---- ctx += attn_w[32x32] @ V_w[32x32(d-half)] ----
        #pragma unroll
        for (int ks = 0; ks < 4; ks++) {
            uint32_t af[2][4];
            #pragma unroll
            for (int mt = 0; mt < 2; mt++) {
                const float* a = &sEw[(mt * 16 + g) * SES + ks * 8 + c];
                af[mt][0] = __float_as_uint(a[0]);
                af[mt][1] = __float_as_uint(a[8 * SES]);
                af[mt][2] = __float_as_uint(a[4]);
                af[mt][3] = __float_as_uint(a[8 * SES + 4]);
            }
            const int vr0 = (ks * 8 + c) * SVS + wh + half * 32;
            const int vr1 = (ks * 8 + c + 4) * SVS + wh + half * 32;
            #pragma unroll
            for (int nt = 0; nt < 4; nt++) {
                uint32_t vf[2];
                vf[0] = __float_as_uint(sV[vr0 + nt * 8 + g]);
                vf[1] = __float_as_uint(sV[vr1 + nt * 8 + g]);
                #pragma unroll
                for (int mt = 0; mt < 2; mt++)
                    MMA8(ctxf[mt][nt], af[mt], vf);
            }
        }
    }

    // ---- epilogue: warp writes 32 q x 32 d (its d-half) ----
    #pragma unroll
    for (int mt = 0; mt < 2; mt++) {
        const size_t row = bT + q0 + mt * 16 + g;
        #pragma unroll
        for (int nt = 0; nt < 4; nt++) {
            const int dcol = wh + half * 32 + nt * 8 + 2 * c;
            *(float2*)&g_ctx[row * DDM + dcol] =
                make_float2(ctxf[mt][nt][0], ctxf[mt][nt][1]);
            *(float2*)&g_ctx[(row + 8) * DDM + dcol] =
                make_float2(ctxf[mt][nt][2], ctxf[mt][nt][3]);
        }
    }
}

// ---------------------------------------------------------------------------
// Launch
// ---------------------------------------------------------------------------
extern "C" void kernel_launch(void* const* d_in, const int* in_sizes, int n_in,
                              void* d_out, int out_size)
{
    const float* q  = (const float*)d_in[0];
    const float* k  = (const float*)d_in[1];
    const float* v  = (const float*)d_in[2];
    const float* Wq = (const float*)d_in[3];
    const float* bq = (const float*)d_in[4];
    const float* Wk = (const float*)d_in[5];
    const float* bk = (const float*)d_in[6];
    // d_in[7]=Wv, d_in[8]=bv intentionally unused (reference bug preserved)
    const float* Wc = (const float*)d_in[9];
    const float* bc = (const float*)d_in[10];
    float* out = (float*)d_out;

    cudaFuncSetAttribute(fa_kernel,
                         cudaFuncAttributeMaxDynamicSharedMemorySize,
                         FA_SMEM_BYTES);

    // merged q/k/v projections: grid.z = 3 (z=2 uses Wk/bk -> v: bug preserved)
    proj_mma<<<dim3(DDM / 128, MM / 128, 3), 256>>>(q, k, v, Wq, Wk, bq, bk,
                                                    nullptr, 1);

    fa_kernel<<<dim3(TT / 32, BB), 512, FA_SMEM_BYTES>>>();

    // output projection: g_ctx @ Wc + bc -> out
    proj_mma<<<dim3(DDM / 128, MM / 128, 1), 256>>>(nullptr, nullptr, nullptr,
                                                    Wc, nullptr, bc, nullptr,
                                                    out, 0);
}

// round 12
// speedup vs baseline: 1.0863x; 1.0863x over previous
#include <cuda_runtime.h>
#include <math.h>
#include <stdint.h>

// Problem constants
#define BB  4
#define TT  2048
#define DDM 512
#define HH  8
#define HDM 64
#define MM  (BB*TT)

// ---------------------------------------------------------------------------
// Scratch
// ---------------------------------------------------------------------------
static __device__ float g_qp [MM * DDM];
static __device__ float g_kp [MM * DDM];
static __device__ float g_vp [MM * DDM];
static __device__ float g_ctx[MM * DDM];

// ---------------------------------------------------------------------------
// tf32 / async helpers (plain sm_80+ PTX — valid at compute_100)
// ---------------------------------------------------------------------------
__device__ __forceinline__ uint32_t tf32u(float x) {
    uint32_t r;
    asm("cvt.rna.tf32.f32 %0, %1;" : "=r"(r) : "f"(x));
    return r;
}
__device__ __forceinline__ float tf32f(float x) {
    return __uint_as_float(tf32u(x));
}
__device__ __forceinline__ uint32_t su32(const void* p) {
    uint32_t a;
    asm("{ .reg .u64 t; cvta.to.shared.u64 t, %1; cvt.u32.u64 %0, t; }" : "=r"(a) : "l"(p));
    return a;
}
__device__ __forceinline__ void cp16(uint32_t s, const void* g) {
    asm volatile("cp.async.cg.shared.global [%0], [%1], 16;" :: "r"(s), "l"(g) : "memory");
}
#define CP_COMMIT() asm volatile("cp.async.commit_group;" ::: "memory")
#define CP_WAIT0()  asm volatile("cp.async.wait_group 0;" ::: "memory")
#define CP_WAIT1()  asm volatile("cp.async.wait_group 1;" ::: "memory")

// D(4xf32) += A(4xtf32) * B(2xtf32), m16n8k8
#define MMA8(d, a, b) \
    asm volatile("mma.sync.aligned.m16n8k8.row.col.f32.tf32.tf32.f32 " \
        "{%0,%1,%2,%3}, {%4,%5,%6,%7}, {%8,%9}, {%0,%1,%2,%3};" \
        : "+f"((d)[0]), "+f"((d)[1]), "+f"((d)[2]), "+f"((d)[3]) \
        : "r"((a)[0]), "r"((a)[1]), "r"((a)[2]), "r"((a)[3]), \
          "r"((b)[0]), "r"((b)[1]))

// ---------------------------------------------------------------------------
// Kernel 1: projection GEMM  C[8192,512] = A @ W + bias   (tf32 HMMA)
// mode 1: z-batched qkv (plain stores, tf32-rounded outputs).
// mode 0: single GEMM  g_ctx @ Wc + bc -> Cext (f32 out).
// ---------------------------------------------------------------------------
__global__ __launch_bounds__(256)
void proj_mma(const float* __restrict__ Aq, const float* __restrict__ Ak,
              const float* __restrict__ Av,
              const float* __restrict__ Wq_, const float* __restrict__ Wk_,
              const float* __restrict__ bq_, const float* __restrict__ bk_,
              float* __restrict__ Cext, int mode)
{
    const float* A;
    const float* W;
    const float* bias;
    float* C;
    int round_out;
    if (mode == 1) {
        const int z = blockIdx.z;
        A = (z == 0) ? Aq : (z == 1) ? Ak : Av;
        W = (z == 0) ? Wq_ : Wk_;
        bias = (z == 0) ? bq_ : bk_;
        C = (z == 0) ? g_qp : (z == 1) ? g_kp : g_vp;
        round_out = 1;
    } else {
        A = g_ctx; W = Wq_; bias = bq_; C = Cext;
        round_out = 0;
    }

    __shared__ float sA[4 * 128 * 12];   // 24 KB
    __shared__ float sB[4 * 8 * 136];    // 17.4 KB

    const int tid  = threadIdx.x;
    const int wid  = tid >> 5;
    const int lane = tid & 31;
    const int g    = lane >> 2;
    const int c    = lane & 3;
    const int wm   = wid >> 2;
    const int wn   = wid & 3;
    const int m0   = blockIdx.y * 128;
    const int n0   = blockIdx.x * 128;

    int ar[4], ac4[4], bk_i[4], bn4[4];
    #pragma unroll
    for (int i = 0; i < 4; i++) {
        int idx = tid + 256 * i;
        ar[i]   = idx >> 3;      ac4[i] = idx & 7;
        bk_i[i] = idx >> 5;      bn4[i] = idx & 31;
    }

    float df[4][4][4];
    #pragma unroll
    for (int mt = 0; mt < 4; mt++)
        #pragma unroll
        for (int nt = 0; nt < 4; nt++)
            #pragma unroll
            for (int j = 0; j < 4; j++) df[mt][nt][j] = 0.f;

    float4 pa[4], pb[4];
    #pragma unroll
    for (int i = 0; i < 4; i++) {
        pa[i] = *(const float4*)&A[(size_t)(m0 + ar[i]) * DDM + ac4[i] * 4];
        pb[i] = *(const float4*)&W[(size_t)bk_i[i] * DDM + n0 + bn4[i] * 4];
    }

    for (int it = 0; it < 16; it++) {
        #pragma unroll
        for (int i = 0; i < 4; i++) {
            float4 v = pa[i];
            v.x = tf32f(v.x); v.y = tf32f(v.y); v.z = tf32f(v.z); v.w = tf32f(v.w);
            *(float4*)&sA[((ac4[i] >> 1) * 128 + ar[i]) * 12 + (ac4[i] & 1) * 4] = v;
            float4 u = pb[i];
            u.x = tf32f(u.x); u.y = tf32f(u.y); u.z = tf32f(u.z); u.w = tf32f(u.w);
            *(float4*)&sB[((bk_i[i] >> 3) * 8 + (bk_i[i] & 7)) * 136 + bn4[i] * 4] = u;
        }
        __syncthreads();

        if (it < 15) {
            const int kc = (it + 1) * 32;
            #pragma unroll
            for (int i = 0; i < 4; i++) {
                pa[i] = *(const float4*)&A[(size_t)(m0 + ar[i]) * DDM + kc + ac4[i] * 4];
                pb[i] = *(const float4*)&W[(size_t)(kc + bk_i[i]) * DDM + n0 + bn4[i] * 4];
            }
        }

        #pragma unroll
        for (int s4 = 0; s4 < 4; s4++) {
            uint32_t bf[4][2];
            #pragma unroll
            for (int nt = 0; nt < 4; nt++) {
                int n = wn * 32 + nt * 8 + g;
                bf[nt][0] = __float_as_uint(sB[(s4 * 8 + c)     * 136 + n]);
                bf[nt][1] = __float_as_uint(sB[(s4 * 8 + c + 4) * 136 + n]);
            }
            #pragma unroll
            for (int mt = 0; mt < 4; mt++) {
                int m = wm * 64 + mt * 16 + g;
                uint32_t af[4];
                af[0] = __float_as_uint(sA[(s4 * 128 + m)     * 12 + c]);
                af[1] = __float_as_uint(sA[(s4 * 128 + m + 8) * 12 + c]);
                af[2] = __float_as_uint(sA[(s4 * 128 + m)     * 12 + c + 4]);
                af[3] = __float_as_uint(sA[(s4 * 128 + m + 8) * 12 + c + 4]);
                #pragma unroll
                for (int nt = 0; nt < 4; nt++)
                    MMA8(df[mt][nt], af, bf[nt]);
            }
        }
        __syncthreads();
    }

    #pragma unroll
    for (int nt = 0; nt < 4; nt++) {
        const int col = n0 + wn * 32 + nt * 8 + 2 * c;
        const float b0 = bias[col], b1 = bias[col + 1];
        #pragma unroll
        for (int mt = 0; mt < 4; mt++) {
            const int row = m0 + wm * 64 + mt * 16 + g;
            float o00 = df[mt][nt][0] + b0, o01 = df[mt][nt][1] + b1;
            float o10 = df[mt][nt][2] + b0, o11 = df[mt][nt][3] + b1;
            if (round_out) {
                o00 = tf32f(o00); o01 = tf32f(o01);
                o10 = tf32f(o10); o11 = tf32f(o11);
            }
            *(float2*)&C[(size_t)row * DDM + col]       = make_float2(o00, o01);
            *(float2*)&C[(size_t)(row + 8) * DDM + col] = make_float2(o10, o11);
        }
    }
}

// ---------------------------------------------------------------------------
// Kernel 2: fused attention, tf32 HMMA, 512 threads / 16 warps (R9 config).
// warp = (half, head). q-tile 32, k-chunk 32. Single K/V smem buffers,
// cp.async producer schedule: V(kt) issued at chunk top (consumed at B3),
// K(kt+1) issued after B2. 3 barriers/chunk, staging latency hidden.
// qp/kp/vp are pre-rounded tf32 in gmem -> staging is a pure async copy.
// ---------------------------------------------------------------------------
#define SKS 516                    // sK row stride (floats)
#define SVS 520                    // sV row stride
#define SES 36                     // sE q-row stride (32 k + 4 pad)
#define SEH (32 * SES)             // sE head stride
#define FA_SMEM_BYTES ((32*SKS + 32*SVS + 8*SEH) * 4)
#define L2E8 0.18033688f           // log2(e)/8

__global__ __launch_bounds__(512, 1)
void fa_kernel(void)
{
    extern __shared__ float sm[];
    float* sK = sm;                        // [32][516]
    float* sV = sm + 32 * SKS;             // [32][520]
    float* sE = sm + 32 * SKS + 32 * SVS;  // [8][32][36]

    const int tid  = threadIdx.x;
    const int wid  = tid >> 5;
    const int w    = wid & 7;              // head
    const int half = wid >> 3;             // q-half: rows half*16 .. +15
    const int lane = tid & 31;
    const int g    = lane >> 2;
    const int c    = lane & 3;
    const int q0   = blockIdx.x * 32;
    const size_t bT = (size_t)blockIdx.y * TT;

    float* sEw = sE + w * SEH;
    const int wh = w * HDM;

    // staging map: 8 x cp16 per thread per tensor per chunk
    const int str  = tid >> 7;             // base row 0..3 (advances by 4)
    const int sc4  = tid & 127;            // float4 col 0..127
    const uint32_t sKa = su32(sK) + (str * SKS + sc4 * 4) * 4;
    const uint32_t sVa = su32(sV) + (str * SVS + sc4 * 4) * 4;
    const float* gK = g_kp + (bT + str) * DDM + sc4 * 4;
    const float* gV = g_vp + (bT + str) * DDM + sc4 * 4;

    // ---- persistent Q fragments: 16 q-rows x 64 d for head w (tf32 in gmem) ----
    uint32_t qf[8][4];
    {
        const size_t r0 = bT + q0 + half * 16 + g;
        #pragma unroll
        for (int ds = 0; ds < 8; ds++) {
            const int col = wh + ds * 8 + c;
            qf[ds][0] = __float_as_uint(g_qp[r0 * DDM + col]);
            qf[ds][1] = __float_as_uint(g_qp[(r0 + 8) * DDM + col]);
            qf[ds][2] = __float_as_uint(g_qp[r0 * DDM + col + 4]);
            qf[ds][3] = __float_as_uint(g_qp[(r0 + 8) * DDM + col + 4]);
        }
    }

    float ctxf[8][4];
    #pragma unroll
    for (int nt = 0; nt < 8; nt++)
        #pragma unroll
        for (int j = 0; j < 4; j++) ctxf[nt][j] = 0.f;

    // ---- prologue: async-issue K(0) ----
    #pragma unroll
    for (int i = 0; i < 8; i++)
        cp16(sKa + i * (4 * SKS * 4), gK + (size_t)(4 * i) * DDM);
    CP_COMMIT();

    for (int kt = 0; kt < TT / 32; kt++) {
        const int k0 = kt * 32;

        CP_WAIT0();          // K(kt) arrived (everything older drained)
        __syncthreads();     // B1: K visible; ctx(kt-1) done with sV/sE

        // ---- async-issue V(kt) (consumed at B3, hidden behind S+softmax) ----
        #pragma unroll
        for (int i = 0; i < 8; i++)
            cp16(sVa + i * (4 * SVS * 4), gV + (size_t)(k0 + 4 * i) * DDM);
        CP_COMMIT();

        // ---- S = Q_w[16x64] @ K_w^T[64x32] ----
        float sf[4][4];
        #pragma unroll
        for (int nt = 0; nt < 4; nt++)
            #pragma unroll
            for (int j = 0; j < 4; j++) sf[nt][j] = 0.f;

        #pragma unroll
        for (int ds = 0; ds < 8; ds++) {
            const int dcol = wh + ds * 8 + c;
            #pragma unroll
            for (int nt = 0; nt < 4; nt++) {
                uint32_t bf[2];
                const int krow = nt * 8 + g;
                bf[0] = __float_as_uint(sK[krow * SKS + dcol]);
                bf[1] = __float_as_uint(sK[krow * SKS + dcol + 4]);
                MMA8(sf[nt], qf[ds], bf);
            }
        }

        // ---- write S frags to exchange buffer sE[head][q][k] ----
        #pragma unroll
        for (int nt = 0; nt < 4; nt++) {
            float* e = &sEw[(half * 16 + g) * SES + nt * 8 + 2 * c];
            *(float2*)e             = make_float2(sf[nt][0], sf[nt][1]);
            *(float2*)(e + 8 * SES) = make_float2(sf[nt][2], sf[nt][3]);
        }
        __syncthreads();     // B2: sE complete; S done reading sK

        // ---- async-issue K(kt+1) (wraps on last chunk; dead but harmless) ----
        {
            const int kn = ((kt + 1) & 63) * 32;
            #pragma unroll
            for (int i = 0; i < 8; i++)
                cp16(sKa + i * (4 * SKS * 4), gK + (size_t)(kn + 4 * i) * DDM);
            CP_COMMIT();
        }

        // ---- softmax over heads: each thread owns 2 (q,k) elements ----
        {
            const int q  = tid >> 4;            // 0..31
            const int kb = (tid & 15) * 2;      // 0..30
            float2 v[8];
            #pragma unroll
            for (int h = 0; h < 8; h++)
                v[h] = *(const float2*)&sE[h * SEH + q * SES + kb];
            #pragma unroll
            for (int j = 0; j < 2; j++) {
                float m = ((float*)&v[0])[j];
                #pragma unroll
                for (int h = 1; h < 8; h++) m = fmaxf(m, ((float*)&v[h])[j]);
                const float ms = m * L2E8;
                float s = 0.f;
                #pragma unroll
                for (int h = 0; h < 8; h++) {
                    float e = exp2f(fmaf(((float*)&v[h])[j], L2E8, -ms));
                    ((float*)&v[h])[j] = e; s += e;
                }
                const float inv = 1.f / s;
                #pragma unroll
                for (int h = 0; h < 8; h++) ((float*)&v[h])[j] *= inv;
            }
            #pragma unroll
            for (int h = 0; h < 8; h++) {
                float2 o = v[h];
                o.x = tf32f(o.x); o.y = tf32f(o.y);
                *(float2*)&sE[h * SEH + q * SES + kb] = o;
            }
        }

        CP_WAIT1();          // V(kt) arrived (K(kt+1) may remain in flight)
        __syncthreads();     // B3: attn visible; V visible

        // ---- ctx += attn_w[16x32] @ V_w[32x64] ----
        #pragma unroll
        for (int ks = 0; ks < 4; ks++) {
            uint32_t af[4];
            {
                const float* a = &sEw[(half * 16 + g) * SES + ks * 8 + c];
                af[0] = __float_as_uint(a[0]);
                af[1] = __float_as_uint(a[8 * SES]);
                af[2] = __float_as_uint(a[4]);
                af[3] = __float_as_uint(a[8 * SES + 4]);
            }
            const int vr0 = (ks * 8 + c) * SVS + wh;
            const int vr1 = (ks * 8 + c + 4) * SVS + wh;
            #pragma unroll
            for (int nt = 0; nt < 8; nt++) {
                uint32_t vf[2];
                vf[0] = __float_as_uint(sV[vr0 + nt * 8 + g]);
                vf[1] = __float_as_uint(sV[vr1 + nt * 8 + g]);
                MMA8(ctxf[nt], af, vf);
            }
        }
    }

    // ---- epilogue: ctx -> g_ctx[b, q, w*64 + d] ----
    {
        const size_t row = bT + q0 + half * 16 + g;
        #pragma unroll
        for (int nt = 0; nt < 8; nt++) {
            const int dcol = wh + nt * 8 + 2 * c;
            *(float2*)&g_ctx[row * DDM + dcol] =
                make_float2(ctxf[nt][0], ctxf[nt][1]);
            *(float2*)&g_ctx[(row + 8) * DDM + dcol] =
                make_float2(ctxf[nt][2], ctxf[nt][3]);
        }
    }
}

// ---------------------------------------------------------------------------
// Launch
// ---------------------------------------------------------------------------
extern "C" void kernel_launch(void* const* d_in, const int* in_sizes, int n_in,
                              void* d_out, int out_size)
{
    const float* q  = (const float*)d_in[0];
    const float* k  = (const float*)d_in[1];
    const float* v  = (const float*)d_in[2];
    const float* Wq = (const float*)d_in[3];
    const float* bq = (const float*)d_in[4];
    const float* Wk = (const float*)d_in[5];
    const float* bk = (const float*)d_in[6];
    // d_in[7]=Wv, d_in[8]=bv intentionally unused (reference bug preserved)
    const float* Wc = (const float*)d_in[9];
    const float* bc = (const float*)d_in[10];
    float* out = (float*)d_out;

    cudaFuncSetAttribute(fa_kernel,
                         cudaFuncAttributeMaxDynamicSharedMemorySize,
                         FA_SMEM_BYTES);

    // merged q/k/v projections: grid.z = 3 (z=2 uses Wk/bk -> v: bug preserved)
    proj_mma<<<dim3(DDM / 128, MM / 128, 3), 256>>>(q, k, v, Wq, Wk, bq, bk,
                                                    nullptr, 1);

    fa_kernel<<<dim3(TT / 32, BB), 512, FA_SMEM_BYTES>>>();

    // output projection: g_ctx @ Wc + bc -> out
    proj_mma<<<dim3(DDM / 128, MM / 128, 1), 256>>>(nullptr, nullptr, nullptr,
                                                    Wc, nullptr, bc, nullptr,
                                                    out, 0);
}

// round 14
// speedup vs baseline: 1.0994x; 1.0121x over previous
#include <cuda_runtime.h>
#include <math.h>
#include <stdint.h>

// Problem constants
#define BB  4
#define TT  2048
#define DDM 512
#define HH  8
#define HDM 64
#define MM  (BB*TT)

// ---------------------------------------------------------------------------
// Scratch
// ---------------------------------------------------------------------------
static __device__ float g_qp [MM * DDM];
static __device__ float g_kp [MM * DDM];
static __device__ float g_vp [MM * DDM];
static __device__ float g_ctx[MM * DDM];

// ---------------------------------------------------------------------------
// tf32 / async helpers (plain sm_80+ PTX — valid at compute_100)
// ---------------------------------------------------------------------------
__device__ __forceinline__ uint32_t tf32u(float x) {
    uint32_t r;
    asm("cvt.rna.tf32.f32 %0, %1;" : "=r"(r) : "f"(x));
    return r;
}
__device__ __forceinline__ float tf32f(float x) {
    return __uint_as_float(tf32u(x));
}
__device__ __forceinline__ uint32_t su32(const void* p) {
    uint32_t a;
    asm("{ .reg .u64 t; cvta.to.shared.u64 t, %1; cvt.u32.u64 %0, t; }" : "=r"(a) : "l"(p));
    return a;
}
__device__ __forceinline__ void cp16(uint32_t s, const void* g) {
    asm volatile("cp.async.cg.shared.global [%0], [%1], 16;" :: "r"(s), "l"(g) : "memory");
}
#define CP_COMMIT() asm volatile("cp.async.commit_group;" ::: "memory")
#define CP_WAIT0()  asm volatile("cp.async.wait_group 0;" ::: "memory")
#define CP_WAIT1()  asm volatile("cp.async.wait_group 1;" ::: "memory")

// D(4xf32) += A(4xtf32) * B(2xtf32), m16n8k8
#define MMA8(d, a, b) \
    asm volatile("mma.sync.aligned.m16n8k8.row.col.f32.tf32.tf32.f32 " \
        "{%0,%1,%2,%3}, {%4,%5,%6,%7}, {%8,%9}, {%0,%1,%2,%3};" \
        : "+f"((d)[0]), "+f"((d)[1]), "+f"((d)[2]), "+f"((d)[3]) \
        : "r"((a)[0]), "r"((a)[1]), "r"((a)[2]), "r"((a)[3]), \
          "r"((b)[0]), "r"((b)[1]))

// ---------------------------------------------------------------------------
// Kernel 1: projection GEMM  C[8192,512] = A @ W + bias   (tf32 HMMA)
// Double-buffered DYNAMIC smem (84 KB), ONE __syncthreads per k-iter
// (STS to the idle buffer overlaps the MMA burst on the live buffer).
// mode 1: z-batched qkv (tf32-rounded outputs). mode 0: g_ctx @ Wc + bc.
// ---------------------------------------------------------------------------
#define SA_STRIDE (4 * 128 * 12)
#define SB_STRIDE (4 * 8 * 136)
#define PROJ_SMEM_BYTES ((2 * SA_STRIDE + 2 * SB_STRIDE) * 4)   // 83968 B

__global__ __launch_bounds__(256)
void proj_mma(const float* __restrict__ Aq, const float* __restrict__ Ak,
              const float* __restrict__ Av,
              const float* __restrict__ Wq_, const float* __restrict__ Wk_,
              const float* __restrict__ bq_, const float* __restrict__ bk_,
              float* __restrict__ Cext, int mode)
{
    const float* A;
    const float* W;
    const float* bias;
    float* C;
    int round_out;
    if (mode == 1) {
        const int z = blockIdx.z;
        A = (z == 0) ? Aq : (z == 1) ? Ak : Av;
        W = (z == 0) ? Wq_ : Wk_;
        bias = (z == 0) ? bq_ : bk_;
        C = (z == 0) ? g_qp : (z == 1) ? g_kp : g_vp;
        round_out = 1;
    } else {
        A = g_ctx; W = Wq_; bias = bq_; C = Cext;
        round_out = 0;
    }

    extern __shared__ float psm[];
    float* sA = psm;                       // [2][SA_STRIDE]
    float* sB = psm + 2 * SA_STRIDE;       // [2][SB_STRIDE]

    const int tid  = threadIdx.x;
    const int wid  = tid >> 5;
    const int lane = tid & 31;
    const int g    = lane >> 2;
    const int c    = lane & 3;
    const int wm   = wid >> 2;
    const int wn   = wid & 3;
    const int m0   = blockIdx.y * 128;
    const int n0   = blockIdx.x * 128;

    int ar[4], ac4[4], bk_i[4], bn4[4];
    #pragma unroll
    for (int i = 0; i < 4; i++) {
        int idx = tid + 256 * i;
        ar[i]   = idx >> 3;      ac4[i] = idx & 7;
        bk_i[i] = idx >> 5;      bn4[i] = idx & 31;
    }
    // per-thread staging store offsets (within a buffer)
    int sAoff[4], sBoff[4];
    #pragma unroll
    for (int i = 0; i < 4; i++) {
        sAoff[i] = ((ac4[i] >> 1) * 128 + ar[i]) * 12 + (ac4[i] & 1) * 4;
        sBoff[i] = ((bk_i[i] >> 3) * 8 + (bk_i[i] & 7)) * 136 + bn4[i] * 4;
    }

    float df[4][4][4];
    #pragma unroll
    for (int mt = 0; mt < 4; mt++)
        #pragma unroll
        for (int nt = 0; nt < 4; nt++)
            #pragma unroll
            for (int j = 0; j < 4; j++) df[mt][nt][j] = 0.f;

    float4 pa[4], pb[4];

    // ---- prologue: load + stage it=0 into buffer 0 ----
    #pragma unroll
    for (int i = 0; i < 4; i++) {
        pa[i] = *(const float4*)&A[(size_t)(m0 + ar[i]) * DDM + ac4[i] * 4];
        pb[i] = *(const float4*)&W[(size_t)bk_i[i] * DDM + n0 + bn4[i] * 4];
    }
    #pragma unroll
    for (int i = 0; i < 4; i++) {
        float4 v = pa[i];
        v.x = tf32f(v.x); v.y = tf32f(v.y); v.z = tf32f(v.z); v.w = tf32f(v.w);
        *(float4*)&sA[sAoff[i]] = v;
        float4 u = pb[i];
        u.x = tf32f(u.x); u.y = tf32f(u.y); u.z = tf32f(u.z); u.w = tf32f(u.w);
        *(float4*)&sB[sBoff[i]] = u;
    }
    __syncthreads();

    for (int it = 0; it < 16; it++) {
        const int p = it & 1;
        const float* cA = sA + p * SA_STRIDE;
        const float* cB = sB + p * SB_STRIDE;

        // issue gmem loads for it+1 (latency hidden under the MMA burst)
        if (it < 15) {
            const int kc = (it + 1) * 32;
            #pragma unroll
            for (int i = 0; i < 4; i++) {
                pa[i] = *(const float4*)&A[(size_t)(m0 + ar[i]) * DDM + kc + ac4[i] * 4];
                pb[i] = *(const float4*)&W[(size_t)(kc + bk_i[i]) * DDM + n0 + bn4[i] * 4];
            }
        }

        // compute from buffer p
        #pragma unroll
        for (int s4 = 0; s4 < 4; s4++) {
            uint32_t bf[4][2];
            #pragma unroll
            for (int nt = 0; nt < 4; nt++) {
                int n = wn * 32 + nt * 8 + g;
                bf[nt][0] = __float_as_uint(cB[(s4 * 8 + c)     * 136 + n]);
                bf[nt][1] = __float_as_uint(cB[(s4 * 8 + c + 4) * 136 + n]);
            }
            #pragma unroll
            for (int mt = 0; mt < 4; mt++) {
                int m = wm * 64 + mt * 16 + g;
                uint32_t af[4];
                af[0] = __float_as_uint(cA[(s4 * 128 + m)     * 12 + c]);
                af[1] = __float_as_uint(cA[(s4 * 128 + m + 8) * 12 + c]);
                af[2] = __float_as_uint(cA[(s4 * 128 + m)     * 12 + c + 4]);
                af[3] = __float_as_uint(cA[(s4 * 128 + m + 8) * 12 + c + 4]);
                #pragma unroll
                for (int nt = 0; nt < 4; nt++)
                    MMA8(df[mt][nt], af, bf[nt]);
            }
        }

        // stage it+1 into the idle buffer (no barrier needed before stores)
        if (it < 15) {
            float* nA = sA + (1 - p) * SA_STRIDE;
            float* nB = sB + (1 - p) * SB_STRIDE;
            #pragma unroll
            for (int i = 0; i < 4; i++) {
                float4 v = pa[i];
                v.x = tf32f(v.x); v.y = tf32f(v.y); v.z = tf32f(v.z); v.w = tf32f(v.w);
                *(float4*)&nA[sAoff[i]] = v;
                float4 u = pb[i];
                u.x = tf32f(u.x); u.y = tf32f(u.y); u.z = tf32f(u.z); u.w = tf32f(u.w);
                *(float4*)&nB[sBoff[i]] = u;
            }
        }
        __syncthreads();   // single barrier per iter
    }

    #pragma unroll
    for (int nt = 0; nt < 4; nt++) {
        const int col = n0 + wn * 32 + nt * 8 + 2 * c;
        const float b0 = bias[col], b1 = bias[col + 1];
        #pragma unroll
        for (int mt = 0; mt < 4; mt++) {
            const int row = m0 + wm * 64 + mt * 16 + g;
            float o00 = df[mt][nt][0] + b0, o01 = df[mt][nt][1] + b1;
            float o10 = df[mt][nt][2] + b0, o11 = df[mt][nt][3] + b1;
            if (round_out) {
                o00 = tf32f(o00); o01 = tf32f(o01);
                o10 = tf32f(o10); o11 = tf32f(o11);
            }
            *(float2*)&C[(size_t)row * DDM + col]       = make_float2(o00, o01);
            *(float2*)&C[(size_t)(row + 8) * DDM + col] = make_float2(o10, o11);
        }
    }
}

// ---------------------------------------------------------------------------
// Kernel 2: fused attention, tf32 HMMA, 512 threads / 16 warps (R9 config).
// cp.async producer schedule, 3 barriers/chunk. Attn probs stored raw
// (HW tf32 truncation in the ctx MMA; rna rounding dropped).
// ---------------------------------------------------------------------------
#define SKS 516                    // sK row stride (floats)
#define SVS 520                    // sV row stride
#define SES 36                     // sE q-row stride (32 k + 4 pad)
#define SEH (32 * SES)             // sE head stride
#define FA_SMEM_BYTES ((32*SKS + 32*SVS + 8*SEH) * 4)
#define L2E8 0.18033688f           // log2(e)/8

__global__ __launch_bounds__(512, 1)
void fa_kernel(void)
{
    extern __shared__ float sm[];
    float* sK = sm;                        // [32][516]
    float* sV = sm + 32 * SKS;             // [32][520]
    float* sE = sm + 32 * SKS + 32 * SVS;  // [8][32][36]

    const int tid  = threadIdx.x;
    const int wid  = tid >> 5;
    const int w    = wid & 7;              // head
    const int half = wid >> 3;             // q-half: rows half*16 .. +15
    const int lane = tid & 31;
    const int g    = lane >> 2;
    const int c    = lane & 3;
    const int q0   = blockIdx.x * 32;
    const size_t bT = (size_t)blockIdx.y * TT;

    float* sEw = sE + w * SEH;
    const int wh = w * HDM;

    // staging map: 8 x cp16 per thread per tensor per chunk
    const int str  = tid >> 7;
    const int sc4  = tid & 127;
    const uint32_t sKa = su32(sK) + (str * SKS + sc4 * 4) * 4;
    const uint32_t sVa = su32(sV) + (str * SVS + sc4 * 4) * 4;
    const float* gK = g_kp + (bT + str) * DDM + sc4 * 4;
    const float* gV = g_vp + (bT + str) * DDM + sc4 * 4;

    // ---- persistent Q fragments: 16 q-rows x 64 d for head w (tf32 in gmem) ----
    uint32_t qf[8][4];
    {
        const size_t r0 = bT + q0 + half * 16 + g;
        #pragma unroll
        for (int ds = 0; ds < 8; ds++) {
            const int col = wh + ds * 8 + c;
            qf[ds][0] = __float_as_uint(g_qp[r0 * DDM + col]);
            qf[ds][1] = __float_as_uint(g_qp[(r0 + 8) * DDM + col]);
            qf[ds][2] = __float_as_uint(g_qp[r0 * DDM + col + 4]);
            qf[ds][3] = __float_as_uint(g_qp[(r0 + 8) * DDM + col + 4]);
        }
    }

    float ctxf[8][4];
    #pragma unroll
    for (int nt = 0; nt < 8; nt++)
        #pragma unroll
        for (int j = 0; j < 4; j++) ctxf[nt][j] = 0.f;

    // ---- prologue: async-issue K(0) ----
    #pragma unroll
    for (int i = 0; i < 8; i++)
        cp16(sKa + i * (4 * SKS * 4), gK + (size_t)(4 * i) * DDM);
    CP_COMMIT();

    for (int kt = 0; kt < TT / 32; kt++) {
        const int k0 = kt * 32;

        CP_WAIT0();          // K(kt) arrived
        __syncthreads();     // B1: K visible; ctx(kt-1) done with sV/sE

        // ---- async-issue V(kt) ----
        #pragma unroll
        for (int i = 0; i < 8; i++)
            cp16(sVa + i * (4 * SVS * 4), gV + (size_t)(k0 + 4 * i) * DDM);
        CP_COMMIT();

        // ---- S = Q_w[16x64] @ K_w^T[64x32] ----
        float sf[4][4];
        #pragma unroll
        for (int nt = 0; nt < 4; nt++)
            #pragma unroll
            for (int j = 0; j < 4; j++) sf[nt][j] = 0.f;

        #pragma unroll
        for (int ds = 0; ds < 8; ds++) {
            const int dcol = wh + ds * 8 + c;
            #pragma unroll
            for (int nt = 0; nt < 4; nt++) {
                uint32_t bf[2];
                const int krow = nt * 8 + g;
                bf[0] = __float_as_uint(sK[krow * SKS + dcol]);
                bf[1] = __float_as_uint(sK[krow * SKS + dcol + 4]);
                MMA8(sf[nt], qf[ds], bf);
            }
        }

        // ---- write S frags to exchange buffer sE[head][q][k] ----
        #pragma unroll
        for (int nt = 0; nt < 4; nt++) {
            float* e = &sEw[(half * 16 + g) * SES + nt * 8 + 2 * c];
            *(float2*)e             = make_float2(sf[nt][0], sf[nt][1]);
            *(float2*)(e + 8 * SES) = make_float2(sf[nt][2], sf[nt][3]);
        }
        __syncthreads();     // B2: sE complete; S done reading sK

        // ---- async-issue K(kt+1) (wraps on last chunk; dead but harmless) ----
        {
            const int kn = ((kt + 1) & 63) * 32;
            #pragma unroll
            for (int i = 0; i < 8; i++)
                cp16(sKa + i * (4 * SKS * 4), gK + (size_t)(kn + 4 * i) * DDM);
            CP_COMMIT();
        }

        // ---- softmax over heads: each thread owns 2 (q,k) elements ----
        {
            const int q  = tid >> 4;            // 0..31
            const int kb = (tid & 15) * 2;      // 0..30
            float2 v[8];
            #pragma unroll
            for (int h = 0; h < 8; h++)
                v[h] = *(const float2*)&sE[h * SEH + q * SES + kb];
            #pragma unroll
            for (int j = 0; j < 2; j++) {
                float m = ((float*)&v[0])[j];
                #pragma unroll
                for (int h = 1; h < 8; h++) m = fmaxf(m, ((float*)&v[h])[j]);
                const float ms = m * L2E8;
                float s = 0.f;
                #pragma unroll
                for (int h = 0; h < 8; h++) {
                    float e = exp2f(fmaf(((float*)&v[h])[j], L2E8, -ms));
                    ((float*)&v[h])[j] = e; s += e;
                }
                const float inv = 1.f / s;
                #pragma unroll
                for (int h = 0; h < 8; h++) ((float*)&v[h])[j] *= inv;
            }
            // store raw probs — ctx MMA truncates to tf32 (rna dropped)
            #pragma unroll
            for (int h = 0; h < 8; h++)
                *(float2*)&sE[h * SEH + q * SES + kb] = v[h];
        }

        CP_WAIT1();          // V(kt) arrived (K(kt+1) may remain in flight)
        __syncthreads();     // B3: attn visible; V visible

        // ---- ctx += attn_w[16x32] @ V_w[32x64] ----
        #pragma unroll
        for (int ks = 0; ks < 4; ks++) {
            uint32_t af[4];
            {
                const float* a = &sEw[(half * 16 + g) * SES + ks * 8 + c];
                af[0] = __float_as_uint(a[0]);
                af[1] = __float_as_uint(a[8 * SES]);
                af[2] = __float_as_uint(a[4]);
                af[3] = __float_as_uint(a[8 * SES + 4]);
            }
            const int vr0 = (ks * 8 + c) * SVS + wh;
            const int vr1 = (ks * 8 + c + 4) * SVS + wh;
            #pragma unroll
            for (int nt = 0; nt < 8; nt++) {
                uint32_t vf[2];
                vf[0] = __float_as_uint(sV[vr0 + nt * 8 + g]);
                vf[1] = __float_as_uint(sV[vr1 + nt * 8 + g]);
                MMA8(ctxf[nt], af, vf);
            }
        }
    }

    // ---- epilogue: ctx -> g_ctx[b, q, w*64 + d] ----
    {
        const size_t row = bT + q0 + half * 16 + g;
        #pragma unroll
        for (int nt = 0; nt < 8; nt++) {
            const int dcol = wh + nt * 8 + 2 * c;
            *(float2*)&g_ctx[row * DDM + dcol] =
                make_float2(ctxf[nt][0], ctxf[nt][1]);
            *(float2*)&g_ctx[(row + 8) * DDM + dcol] =
                make_float2(ctxf[nt][2], ctxf[nt][3]);
        }
    }
}

// ---------------------------------------------------------------------------
// Launch
// ---------------------------------------------------------------------------
extern "C" void kernel_launch(void* const* d_in, const int* in_sizes, int n_in,
                              void* d_out, int out_size)
{
    const float* q  = (const float*)d_in[0];
    const float* k  = (const float*)d_in[1];
    const float* v  = (const float*)d_in[2];
    const float* Wq = (const float*)d_in[3];
    const float* bq = (const float*)d_in[4];
    const float* Wk = (const float*)d_in[5];
    const float* bk = (const float*)d_in[6];
    // d_in[7]=Wv, d_in[8]=bv intentionally unused (reference bug preserved)
    const float* Wc = (const float*)d_in[9];
    const float* bc = (const float*)d_in[10];
    float* out = (float*)d_out;

    cudaFuncSetAttribute(fa_kernel,
                         cudaFuncAttributeMaxDynamicSharedMemorySize,
                         FA_SMEM_BYTES);
    cudaFuncSetAttribute(proj_mma,
                         cudaFuncAttributeMaxDynamicSharedMemorySize,
                         PROJ_SMEM_BYTES);

    // merged q/k/v projections: grid.z = 3 (z=2 uses Wk/bk -> v: bug preserved)
    proj_mma<<<dim3(DDM / 128, MM / 128, 3), 256, PROJ_SMEM_BYTES>>>(
        q, k, v, Wq, Wk, bq, bk, nullptr, 1);

    fa_kernel<<<dim3(TT / 32, BB), 512, FA_SMEM_BYTES>>>();

    // output projection: g_ctx @ Wc + bc -> out
    proj_mma<<<dim3(DDM / 128, MM / 128, 1), 256, PROJ_SMEM_BYTES>>>(
        nullptr, nullptr, nullptr, Wc, nullptr, bc, nullptr, out, 0);
}